// round 2
// baseline (speedup 1.0000x reference)
#include <cuda_runtime.h>
#include <math.h>

#define THREADS 256
#define MAXN 4096

// Order-preserving float->uint key: key monotonic increasing with float value.
__device__ __forceinline__ unsigned f2key(float v) {
    unsigned u = __float_as_uint(v);
    return u ^ (unsigned)(((int)u >> 31) | 0x80000000u);
}
__device__ __forceinline__ float key2f(unsigned key) {
    unsigned u = (key & 0x80000000u) ? (key ^ 0x80000000u) : ~key;
    return __uint_as_float(u);
}

__global__ void __launch_bounds__(THREADS)
wildcat_kernel(const float* __restrict__ x, float* __restrict__ out,
               int n, int kmax, int kmin, float alpha)
{
    __shared__ float    s_x[MAXN];
    __shared__ unsigned s_hist[2][256];   // [0]=hi (top-k), [1]=lo (bottom-k)
    __shared__ unsigned s_pref[2];
    __shared__ int      s_krem[2];
    __shared__ float    s_red[2][THREADS / 32];

    const int tid  = threadIdx.x;
    const int lane = tid & 31;
    const int wid  = tid >> 5;
    const long long row = blockIdx.x;
    const float* __restrict__ xr = x + row * (long long)n;

    // ---- init ----
    s_hist[0][tid] = 0;
    s_hist[1][tid] = 0;
    if (tid == 0) { s_krem[0] = kmax; s_krem[1] = kmin; s_pref[0] = 0; s_pref[1] = 0; }
    __syncthreads();

    // ---- sweep 0: load row to smem + top-byte histogram (shared by both selects) ----
    for (int base = 0; base < n; base += THREADS) {
        int i = base + tid;
        bool valid = (i < n);
        float v = valid ? xr[i] : 0.0f;
        if (valid) s_x[i] = v;
        unsigned act = __ballot_sync(0xFFFFFFFFu, valid);
        if (valid) {
            unsigned d = f2key(v) >> 24;
            unsigned same = __match_any_sync(act, d);
            if (lane == (__ffs(same) - 1))
                atomicAdd(&s_hist[0][d], __popc(same));
        }
    }
    __syncthreads();

    // ---- resolve byte 3 (both sides read the same full histogram) ----
    if (tid == 0) {                       // kth LARGEST: scan bins high->low
        int krem = s_krem[0]; unsigned cum = 0;
        for (int d = 255; d >= 0; --d) {
            cum += s_hist[0][d];
            if ((int)cum >= krem) {
                s_krem[0] = krem - (int)(cum - s_hist[0][d]);
                s_pref[0] = (unsigned)d;
                break;
            }
        }
    }
    if (tid == 32) {                      // kth SMALLEST: scan bins low->high
        int krem = s_krem[1]; unsigned cum = 0;
        for (int d = 0; d < 256; ++d) {
            cum += s_hist[0][d];
            if ((int)cum >= krem) {
                s_krem[1] = krem - (int)(cum - s_hist[0][d]);
                s_pref[1] = (unsigned)d;
                break;
            }
        }
    }
    __syncthreads();

    // ---- sweeps for bytes 2,1,0: fused hi/lo histograms over smem ----
    for (int p = 2; p >= 0; --p) {
        s_hist[0][tid] = 0;
        s_hist[1][tid] = 0;
        __syncthreads();
        const unsigned prefH = s_pref[0];
        const unsigned prefL = s_pref[1];
        const int shiftPref = 8 * (p + 1);
        const int shiftDig  = 8 * p;

        for (int base = 0; base < n; base += THREADS) {
            int i = base + tid;
            bool valid = (i < n);
            unsigned key = f2key(valid ? s_x[i] : 0.0f);
            unsigned hb = key >> shiftPref;
            unsigned d  = (key >> shiftDig) & 0xFFu;
            bool mh = valid && (hb == prefH);
            bool ml = valid && (hb == prefL);

            unsigned bh = __ballot_sync(0xFFFFFFFFu, mh);
            if (mh) {
                unsigned same = __match_any_sync(bh, d);
                if (lane == (__ffs(same) - 1))
                    atomicAdd(&s_hist[0][d], __popc(same));
            }
            unsigned bl = __ballot_sync(0xFFFFFFFFu, ml);
            if (ml) {
                unsigned same = __match_any_sync(bl, d);
                if (lane == (__ffs(same) - 1))
                    atomicAdd(&s_hist[1][d], __popc(same));
            }
        }
        __syncthreads();

        if (tid == 0) {
            int krem = s_krem[0]; unsigned cum = 0;
            for (int d = 255; d >= 0; --d) {
                cum += s_hist[0][d];
                if ((int)cum >= krem) {
                    s_krem[0] = krem - (int)(cum - s_hist[0][d]);
                    s_pref[0] = (prefH << 8) | (unsigned)d;
                    break;
                }
            }
        }
        if (tid == 32) {
            int krem = s_krem[1]; unsigned cum = 0;
            for (int d = 0; d < 256; ++d) {
                cum += s_hist[1][d];
                if ((int)cum >= krem) {
                    s_krem[1] = krem - (int)(cum - s_hist[1][d]);
                    s_pref[1] = (prefL << 8) | (unsigned)d;
                    break;
                }
            }
        }
        __syncthreads();
    }

    // ---- final sweep: sum strictly-above / strictly-below thresholds ----
    const unsigned keyH = s_pref[0];   // full 32-bit key of kth largest
    const unsigned keyL = s_pref[1];   // full 32-bit key of kth smallest
    float sumT = 0.0f, sumB = 0.0f;
    for (int i = tid; i < n; i += THREADS) {
        float v = s_x[i];
        unsigned key = f2key(v);
        if (key > keyH) sumT += v;
        if (key < keyL) sumB += v;
    }
    #pragma unroll
    for (int o = 16; o > 0; o >>= 1) {
        sumT += __shfl_xor_sync(0xFFFFFFFFu, sumT, o);
        sumB += __shfl_xor_sync(0xFFFFFFFFu, sumB, o);
    }
    if (lane == 0) { s_red[0][wid] = sumT; s_red[1][wid] = sumB; }
    __syncthreads();

    if (tid == 0) {
        float st = 0.0f, sb = 0.0f;
        #pragma unroll
        for (int w = 0; w < THREADS / 32; ++w) { st += s_red[0][w]; sb += s_red[1][w]; }
        // include the residual count of threshold-valued elements (exact tie handling)
        st += (float)s_krem[0] * key2f(keyH);
        sb += (float)s_krem[1] * key2f(keyL);
        out[row] = st / (float)kmax + (alpha / (float)kmin) * sb;
    }
}

extern "C" void kernel_launch(void* const* d_in, const int* in_sizes, int n_in,
                              void* d_out, int out_size)
{
    const float* x = (const float*)d_in[0];
    float* out = (float*)d_out;

    const int rows = out_size;                 // 32*512 = 16384
    const int n = in_sizes[0] / rows;          // 4096
    // Python int(round(0.2*n)) -> 819 for n=4096
    int kmax = (int)lrintf(0.2f * (float)n);
    int kmin = (int)lrintf(0.2f * (float)n);
    if (kmax < 1) kmax = 1;
    if (kmin < 1) kmin = 1;

    wildcat_kernel<<<rows, THREADS>>>(x, out, n, kmax, kmin, 0.7f);
}

// round 3
// speedup vs baseline: 1.6507x; 1.6507x over previous
#include <cuda_runtime.h>
#include <math.h>

#define THREADS 256
#define MAXN 4096

// Order-preserving float->uint key: key monotonic increasing with float value.
__device__ __forceinline__ unsigned f2key(float v) {
    unsigned u = __float_as_uint(v);
    return u ^ (unsigned)(((int)u >> 31) | 0x80000000u);
}
__device__ __forceinline__ float key2f(unsigned key) {
    unsigned u = (key & 0x80000000u) ? (key ^ 0x80000000u) : ~key;
    return __uint_as_float(u);
}

// Warp-collective resolve of the bin containing the krem-th element,
// counting from the TOP (descending bin order). Lane l owns bins
// 255-8l .. 255-8l-7. Returns selected digit and residual rank.
__device__ __forceinline__ void resolve_desc(const unsigned* hist, int krem, int lane,
                                             unsigned &digit, int &krem_out) {
    unsigned c[8]; unsigned s = 0;
    #pragma unroll
    for (int j = 0; j < 8; j++) { c[j] = hist[255 - (lane * 8 + j)]; s += c[j]; }
    unsigned p = s;
    #pragma unroll
    for (int o = 1; o < 32; o <<= 1) {
        unsigned t = __shfl_up_sync(0xFFFFFFFFu, p, o);
        if (lane >= o) p += t;
    }
    unsigned excl = p - s;
    bool cross = (excl < (unsigned)krem) && (p >= (unsigned)krem);
    unsigned m = __ballot_sync(0xFFFFFFFFu, cross);
    int src = __ffs(m) - 1;
    unsigned dsel = 0; int k2 = 0;
    if (lane == src) {
        unsigned cum = excl;
        #pragma unroll
        for (int j = 0; j < 8; j++) {
            if (cum + c[j] >= (unsigned)krem) {
                dsel = 255u - (unsigned)(lane * 8 + j);
                k2 = krem - (int)cum;
                break;
            }
            cum += c[j];
        }
    }
    digit = __shfl_sync(0xFFFFFFFFu, dsel, src);
    krem_out = __shfl_sync(0xFFFFFFFFu, k2, src);
}

// Same, counting from the BOTTOM (ascending bin order).
__device__ __forceinline__ void resolve_asc(const unsigned* hist, int krem, int lane,
                                            unsigned &digit, int &krem_out) {
    unsigned c[8]; unsigned s = 0;
    #pragma unroll
    for (int j = 0; j < 8; j++) { c[j] = hist[lane * 8 + j]; s += c[j]; }
    unsigned p = s;
    #pragma unroll
    for (int o = 1; o < 32; o <<= 1) {
        unsigned t = __shfl_up_sync(0xFFFFFFFFu, p, o);
        if (lane >= o) p += t;
    }
    unsigned excl = p - s;
    bool cross = (excl < (unsigned)krem) && (p >= (unsigned)krem);
    unsigned m = __ballot_sync(0xFFFFFFFFu, cross);
    int src = __ffs(m) - 1;
    unsigned dsel = 0; int k2 = 0;
    if (lane == src) {
        unsigned cum = excl;
        #pragma unroll
        for (int j = 0; j < 8; j++) {
            if (cum + c[j] >= (unsigned)krem) {
                dsel = (unsigned)(lane * 8 + j);
                k2 = krem - (int)cum;
                break;
            }
            cum += c[j];
        }
    }
    digit = __shfl_sync(0xFFFFFFFFu, dsel, src);
    krem_out = __shfl_sync(0xFFFFFFFFu, k2, src);
}

__global__ void __launch_bounds__(THREADS)
wildcat_kernel(const float* __restrict__ x, float* __restrict__ out,
               int n, int kmax, int kmin, float alpha)
{
    __shared__ float          s_x[MAXN];
    __shared__ unsigned short s_cand[MAXN];   // H candidates grow from 0, L from n-1
    __shared__ unsigned       s_hist[2][256];
    __shared__ unsigned       s_pref[2];
    __shared__ int            s_krem[2];
    __shared__ int            s_cntH, s_cntL;
    __shared__ float          s_red[2][THREADS / 32];

    const int tid  = threadIdx.x;
    const int lane = tid & 31;
    const int wid  = tid >> 5;
    const long long row = blockIdx.x;
    const float* __restrict__ xr = x + row * (long long)n;

    s_hist[0][tid] = 0;
    s_hist[1][tid] = 0;
    if (tid == 0) { s_cntH = 0; s_cntL = 0; }
    __syncthreads();

    // ================= pass 1: vectorized load + byte-3 histogram =============
    const int n4 = n >> 2;
    const float4* __restrict__ xr4 = (const float4*)xr;
    float4* sx4 = (float4*)s_x;
    const int nv4 = (n4 / THREADS) * THREADS;     // uniform vector portion
    for (int i = tid; i < nv4; i += THREADS) {
        float4 v = xr4[i];
        sx4[i] = v;
        float vv[4] = {v.x, v.y, v.z, v.w};
        #pragma unroll
        for (int j = 0; j < 4; j++) {
            unsigned d = f2key(vv[j]) >> 24;
            unsigned same = __match_any_sync(0xFFFFFFFFu, d);
            if ((__ffs(same) - 1) == lane)
                atomicAdd(&s_hist[0][d], __popc(same));
        }
    }
    // scalar tail (none for n=4096, kept for generality)
    for (int base = nv4 * 4; base < n; base += THREADS) {
        int i = base + tid;
        bool valid = (i < n);
        float v = valid ? xr[i] : 0.0f;
        if (valid) s_x[i] = v;
        unsigned act = __ballot_sync(0xFFFFFFFFu, valid);
        if (valid) {
            unsigned d = f2key(v) >> 24;
            unsigned same = __match_any_sync(act, d);
            if ((__ffs(same) - 1) == lane)
                atomicAdd(&s_hist[0][d], __popc(same));
        }
    }
    __syncthreads();

    // ---- resolve byte 3 (both sides share the full histogram) ----
    if (wid == 0) {
        unsigned d; int k2;
        resolve_desc(s_hist[0], kmax, lane, d, k2);
        if (lane == 0) { s_pref[0] = d; s_krem[0] = k2; }
    } else if (wid == 1) {
        unsigned d; int k2;
        resolve_asc(s_hist[0], kmin, lane, d, k2);
        if (lane == 0) { s_pref[1] = d; s_krem[1] = k2; }
    }
    __syncthreads();
    const unsigned dH = s_pref[0];
    const unsigned dL = s_pref[1];
    const bool same3 = (dH == dL);
    s_hist[0][tid] = 0;
    s_hist[1][tid] = 0;
    __syncthreads();

    // ===== pass 2: compact candidates + inline byte-2 histograms ==============
    for (int base = 0; base < n; base += THREADS) {
        int i = base + tid;
        bool valid = (i < n);
        unsigned key = f2key(valid ? s_x[i] : 0.0f);
        unsigned b3 = key >> 24;

        bool mh = valid && (b3 == dH);
        unsigned bm = __ballot_sync(0xFFFFFFFFu, mh);
        if (mh) {
            int leader = __ffs(bm) - 1;
            int bbase;
            if (lane == leader) bbase = atomicAdd(&s_cntH, __popc(bm));
            bbase = __shfl_sync(bm, bbase, leader);
            int r = __popc(bm & ((1u << lane) - 1u));
            s_cand[bbase + r] = (unsigned short)i;
            atomicAdd(&s_hist[0][(key >> 16) & 0xFFu], 1u);
        }
        if (!same3) {
            bool ml = valid && (b3 == dL);
            unsigned bl = __ballot_sync(0xFFFFFFFFu, ml);
            if (ml) {
                int leader = __ffs(bl) - 1;
                int bbase;
                if (lane == leader) bbase = atomicAdd(&s_cntL, __popc(bl));
                bbase = __shfl_sync(bl, bbase, leader);
                int r = __popc(bl & ((1u << lane) - 1u));
                s_cand[n - 1 - (bbase + r)] = (unsigned short)i;
                atomicAdd(&s_hist[1][(key >> 16) & 0xFFu], 1u);
            }
        }
    }
    __syncthreads();

    // ---- resolve byte 2 ----
    if (wid == 0) {
        unsigned d; int k2;
        resolve_desc(s_hist[0], s_krem[0], lane, d, k2);
        if (lane == 0) { s_pref[0] = (dH << 8) | d; s_krem[0] = k2; }
    } else if (wid == 1) {
        unsigned d; int k2;
        resolve_asc(s_hist[same3 ? 0 : 1], s_krem[1], lane, d, k2);
        if (lane == 0) { s_pref[1] = (dL << 8) | d; s_krem[1] = k2; }
    }
    __syncthreads();
    const int cntH = s_cntH;
    const int cntL = same3 ? cntH : s_cntL;
    const unsigned prefH2 = s_pref[0];
    const unsigned prefL2 = s_pref[1];
    s_hist[0][tid] = 0;
    s_hist[1][tid] = 0;
    __syncthreads();

    // ===== pass 3: byte-1 histograms over candidate lists =====================
    for (int t = tid; t < cntH; t += THREADS) {
        unsigned key = f2key(s_x[s_cand[t]]);
        if ((key >> 16) == prefH2) atomicAdd(&s_hist[0][(key >> 8) & 0xFFu], 1u);
    }
    for (int t = tid; t < cntL; t += THREADS) {
        int idx = same3 ? (int)s_cand[t] : (int)s_cand[n - 1 - t];
        unsigned key = f2key(s_x[idx]);
        if ((key >> 16) == prefL2) atomicAdd(&s_hist[1][(key >> 8) & 0xFFu], 1u);
    }
    __syncthreads();

    // ---- resolve byte 1 ----
    if (wid == 0) {
        unsigned d; int k2;
        resolve_desc(s_hist[0], s_krem[0], lane, d, k2);
        if (lane == 0) { s_pref[0] = (prefH2 << 8) | d; s_krem[0] = k2; }
    } else if (wid == 1) {
        unsigned d; int k2;
        resolve_asc(s_hist[1], s_krem[1], lane, d, k2);
        if (lane == 0) { s_pref[1] = (prefL2 << 8) | d; s_krem[1] = k2; }
    }
    __syncthreads();
    const unsigned prefH3 = s_pref[0];
    const unsigned prefL3 = s_pref[1];
    s_hist[0][tid] = 0;
    s_hist[1][tid] = 0;
    __syncthreads();

    // ===== pass 4: byte-0 histograms over candidate lists ======================
    for (int t = tid; t < cntH; t += THREADS) {
        unsigned key = f2key(s_x[s_cand[t]]);
        if ((key >> 8) == prefH3) atomicAdd(&s_hist[0][key & 0xFFu], 1u);
    }
    for (int t = tid; t < cntL; t += THREADS) {
        int idx = same3 ? (int)s_cand[t] : (int)s_cand[n - 1 - t];
        unsigned key = f2key(s_x[idx]);
        if ((key >> 8) == prefL3) atomicAdd(&s_hist[1][key & 0xFFu], 1u);
    }
    __syncthreads();

    // ---- resolve byte 0 -> full 32-bit threshold keys ----
    if (wid == 0) {
        unsigned d; int k2;
        resolve_desc(s_hist[0], s_krem[0], lane, d, k2);
        if (lane == 0) { s_pref[0] = (prefH3 << 8) | d; s_krem[0] = k2; }
    } else if (wid == 1) {
        unsigned d; int k2;
        resolve_asc(s_hist[1], s_krem[1], lane, d, k2);
        if (lane == 0) { s_pref[1] = (prefL3 << 8) | d; s_krem[1] = k2; }
    }
    __syncthreads();

    const unsigned keyH = s_pref[0];
    const unsigned keyL = s_pref[1];

    // ===== final sweep: sum strictly-above / strictly-below (vectorized) ======
    float sumT = 0.0f, sumB = 0.0f;
    for (int i = tid; i < nv4; i += THREADS) {
        float4 v = sx4[i];
        float vv[4] = {v.x, v.y, v.z, v.w};
        #pragma unroll
        for (int j = 0; j < 4; j++) {
            unsigned key = f2key(vv[j]);
            if (key > keyH) sumT += vv[j];
            if (key < keyL) sumB += vv[j];
        }
    }
    for (int i = nv4 * 4 + tid; i < n; i += THREADS) {
        float v = s_x[i];
        unsigned key = f2key(v);
        if (key > keyH) sumT += v;
        if (key < keyL) sumB += v;
    }
    #pragma unroll
    for (int o = 16; o > 0; o >>= 1) {
        sumT += __shfl_xor_sync(0xFFFFFFFFu, sumT, o);
        sumB += __shfl_xor_sync(0xFFFFFFFFu, sumB, o);
    }
    if (lane == 0) { s_red[0][wid] = sumT; s_red[1][wid] = sumB; }
    __syncthreads();

    if (tid == 0) {
        float st = 0.0f, sb = 0.0f;
        #pragma unroll
        for (int w = 0; w < THREADS / 32; ++w) { st += s_red[0][w]; sb += s_red[1][w]; }
        st += (float)s_krem[0] * key2f(keyH);   // exact tie handling
        sb += (float)s_krem[1] * key2f(keyL);
        out[row] = st / (float)kmax + (alpha / (float)kmin) * sb;
    }
}

extern "C" void kernel_launch(void* const* d_in, const int* in_sizes, int n_in,
                              void* d_out, int out_size)
{
    const float* x = (const float*)d_in[0];
    float* out = (float*)d_out;

    const int rows = out_size;                 // 32*512 = 16384
    const int n = in_sizes[0] / rows;          // 4096
    int kmax = (int)lrintf(0.2f * (float)n);   // int(round(0.2*n)) = 819
    int kmin = (int)lrintf(0.2f * (float)n);
    if (kmax < 1) kmax = 1;
    if (kmin < 1) kmin = 1;

    wildcat_kernel<<<rows, THREADS>>>(x, out, n, kmax, kmin, 0.7f);
}